// round 3
// baseline (speedup 1.0000x reference)
#include <cuda_runtime.h>
#include <cstdint>

// Problem constants
#define N_ROWS 8192
#define D_DIM  64
#define B_HALF 1024          // exploit epsilon = [tmp; -tmp] antisymmetry
#define TWO_PI 6.283185307179586f

// Tiling
#define TB 128               // threads per block == rows per block
#define NG 16                // split of the b dimension across blocks
#define BC (B_HALF / NG)     // 64 basis rows per block

typedef unsigned long long u64;

// Packed f32x2 math (Blackwell FFMA2 — 2x fp32 throughput per instruction)
#define FMA2(d, a, b, c) asm("fma.rn.f32x2 %0, %1, %2, %3;" : "=l"(d) : "l"(a), "l"(b), "l"(c))
#define ADD2(d, a, b)    asm("add.rn.f32x2 %0, %1, %2;"     : "=l"(d) : "l"(a), "l"(b))
#define PACK2(d, lo, hi) asm("mov.b64 %0, {%1, %2};"        : "=l"(d) : "f"(lo), "f"(hi))
#define UNPACK2(lo, hi, s) asm("mov.b64 {%0, %1}, %2;"      : "=f"(lo), "=f"(hi) : "l"(s))

// Scratch (static device allocation is the sanctioned workaround)
__device__ float g_S[B_HALF * D_DIM];     // s[b][j] = eps[b][j] / (2*pi*lam[j])
__device__ float g_M[B_HALF * D_DIM];     // mat[b][i]
__device__ float g_ws[B_HALF];            // -(w_s[b] + w_s[b+1024])
__device__ float g_wc[B_HALF];            //  (w_c[b] - w_c[b+1024])
__device__ float g_part[NG * N_ROWS * D_DIM];   // 32 MB partials

// ---------------------------------------------------------------------------
// Precompute S, mat, effective weights. 1024*64 = 65536 threads.
// ---------------------------------------------------------------------------
__global__ void prep_kernel(const float* __restrict__ eps,
                            const float* __restrict__ lam,
                            const float* __restrict__ eta,
                            const float* __restrict__ w) {
    int idx = blockIdx.x * blockDim.x + threadIdx.x;
    if (idx < B_HALF * D_DIM) {
        int b = idx >> 6;
        int j = idx & 63;
        float l = lam[j];
        g_S[idx] = eps[idx] / (TWO_PI * l);
        float eta2 = eta[0] * eta[0];
        float m;
        if (j < 32) {
            // mat[b][i<32] = eps[b][32+i] / lam[32+i]
            m = eps[b * 64 + 32 + j] / lam[32 + j];
        } else {
            // mat[b][i>=32] = -eps[b][i-32]/lam[i-32] - eta^2 * eps[b][i]/lam[i]
            m = -eps[b * 64 + (j - 32)] / lam[j - 32] - eta2 * eps[idx] / l;
        }
        g_M[idx] = m;
    }
    if (idx < B_HALF) {
        g_ws[idx] = -(w[idx] + w[idx + B_HALF]);
        g_wc[idx] = w[2 * B_HALF + idx] - w[3 * B_HALF + idx];
    }
}

// ---------------------------------------------------------------------------
// Main fused kernel. Block = (row tile of 128, b-group of 64).
// Each thread owns one row: x in 32 packed regs, acc in 32 packed regs.
// ---------------------------------------------------------------------------
__global__ void __launch_bounds__(TB, 3)
main_kernel(const float* __restrict__ x) {
    __shared__ __align__(16) float sS[BC * D_DIM];
    __shared__ __align__(16) float sM[BC * D_DIM];
    __shared__ float sW[2 * BC];

    const int tid = threadIdx.x;
    const int row = blockIdx.x * TB + tid;
    const int g   = blockIdx.y;
    const int b0  = g * BC;

    // Stage S / mat tiles into shared memory (vectorized, coalesced)
    {
        const float4* gS4 = reinterpret_cast<const float4*>(g_S + b0 * D_DIM);
        const float4* gM4 = reinterpret_cast<const float4*>(g_M + b0 * D_DIM);
        float4* sS4 = reinterpret_cast<float4*>(sS);
        float4* sM4 = reinterpret_cast<float4*>(sM);
        #pragma unroll
        for (int i = tid; i < BC * (D_DIM / 4); i += TB) {
            sS4[i] = gS4[i];
            sM4[i] = gM4[i];
        }
        if (tid < BC) {
            sW[2 * tid]     = g_ws[b0 + tid];
            sW[2 * tid + 1] = g_wc[b0 + tid];
        }
    }

    // Load this thread's x row into packed registers (32 x f32x2)
    u64 x2[32];
    {
        const u64* xr = reinterpret_cast<const u64*>(x + (size_t)row * D_DIM);
        #pragma unroll
        for (int k = 0; k < 32; ++k) x2[k] = xr[k];
    }

    u64 acc2[32];
    #pragma unroll
    for (int k = 0; k < 32; ++k) acc2[k] = 0ull;   // (0.0f, 0.0f)

    __syncthreads();

    const u64* sSu = reinterpret_cast<const u64*>(sS);
    const u64* sMu = reinterpret_cast<const u64*>(sM);

    #pragma unroll 1
    for (int bb = 0; bb < BC; ++bb) {
        const u64* Sr = sSu + bb * 32;
        // p = x . s_b   (4 independent packed chains for ILP)
        u64 p0 = 0ull, p1 = 0ull, p2 = 0ull, p3 = 0ull;
        #pragma unroll
        for (int k = 0; k < 32; k += 4) {
            u64 e0 = Sr[k], e1 = Sr[k + 1], e2 = Sr[k + 2], e3 = Sr[k + 3];
            FMA2(p0, x2[k],     e0, p0);
            FMA2(p1, x2[k + 1], e1, p1);
            FMA2(p2, x2[k + 2], e2, p2);
            FMA2(p3, x2[k + 3], e3, p3);
        }
        u64 ps, pt;
        ADD2(ps, p0, p1);
        ADD2(pt, p2, p3);
        ADD2(ps, ps, pt);
        float plo, phi;
        UNPACK2(plo, phi, ps);
        float p = plo + phi;            // p = sim / (2*pi)

        // own range reduction -> theta in [-pi, pi] (MUFU sweet spot)
        float r  = p - rintf(p);
        float th = r * TWO_PI;
        float sn = __sinf(th);
        float cs = __cosf(th);
        float u  = sn * sW[2 * bb] + cs * sW[2 * bb + 1];

        u64 u2;
        PACK2(u2, u, u);

        const u64* Mr = sMu + bb * 32;
        #pragma unroll
        for (int k = 0; k < 32; ++k) {
            FMA2(acc2[k], u2, Mr[k], acc2[k]);
        }
    }

    // Store partial result for this b-group
    {
        u64* dst = reinterpret_cast<u64*>(g_part + ((size_t)g * N_ROWS + row) * D_DIM);
        #pragma unroll
        for (int k = 0; k < 32; ++k) dst[k] = acc2[k];
    }
}

// ---------------------------------------------------------------------------
// Reduce the NG partial buffers into the output.
// ---------------------------------------------------------------------------
__global__ void reduce_kernel(float* __restrict__ out) {
    int idx = blockIdx.x * blockDim.x + threadIdx.x;   // < N_ROWS * D_DIM
    float s = 0.0f;
    #pragma unroll
    for (int g = 0; g < NG; ++g) {
        s += g_part[(size_t)g * (N_ROWS * D_DIM) + idx];
    }
    out[idx] = s;
}

// ---------------------------------------------------------------------------
extern "C" void kernel_launch(void* const* d_in, const int* in_sizes, int n_in,
                              void* d_out, int out_size) {
    // Robust input mapping by element count (t and eta are both size 1;
    // t comes first in metadata order, eta second).
    const float* x   = nullptr;
    const float* eps = nullptr;
    const float* lam = nullptr;
    const float* eta = nullptr;
    const float* w   = nullptr;
    int ones_seen = 0;
    for (int i = 0; i < n_in; ++i) {
        int sz = in_sizes[i];
        const float* p = (const float*)d_in[i];
        if      (sz == N_ROWS * D_DIM)     x   = p;
        else if (sz == 2 * B_HALF * D_DIM) eps = p;
        else if (sz == D_DIM)              lam = p;
        else if (sz == 4 * B_HALF)         w   = p;
        else if (sz == 1) {
            if (ones_seen == 1) eta = p;   // second size-1 input is eta
            ones_seen++;
        }
    }

    prep_kernel<<<(B_HALF * D_DIM + 255) / 256, 256>>>(eps, lam, eta, w);
    main_kernel<<<dim3(N_ROWS / TB, NG), TB>>>(x);
    reduce_kernel<<<(N_ROWS * D_DIM + 255) / 256, 256>>>((float*)d_out);
}

// round 4
// speedup vs baseline: 1.6884x; 1.6884x over previous
#include <cuda_runtime.h>
#include <cstdint>

// Problem constants
#define N_ROWS 8192
#define D_DIM  64
#define B_HALF 1024          // epsilon = [tmp; -tmp] antisymmetry folds B=2048 -> 1024
#define TWO_PI 6.283185307179586f

// Tiling
#define TB      256          // threads per block
#define ROWS_T  128          // rows per block
#define BT      64           // basis per block
#define NG      (B_HALF / BT)   // 16 b-groups

// Shared layout (bytes)
#define SX_STRIDE 132        // floats per k-row of x tile (pad for banks, even for u64)
#define SS_STRIDE 68         // floats per k-row of s tile
#define SU_STRIDE 65         // u64 per b-row of u tile
#define OFF_X  0
#define OFF_S  (64 * SX_STRIDE * 4)                 // 33792
#define OFF_W  (OFF_S + 64 * SS_STRIDE * 4)         // 51200
#define SMEM_BYTES (OFF_W + 2 * BT * 4)             // 51712

typedef unsigned long long u64;

// Packed f32x2 math (Blackwell FFMA2 — full-rate fp32, 2 FMAs per instruction)
#define FMA2(d, a, b, c) asm("fma.rn.f32x2 %0, %1, %2, %3;" : "=l"(d) : "l"(a), "l"(b), "l"(c))
#define PACK2(d, lo, hi) asm("mov.b64 %0, {%1, %2};"        : "=l"(d) : "f"(lo), "f"(hi))
#define UNPACK2(lo, hi, s) asm("mov.b64 {%0, %1}, %2;"      : "=f"(lo), "=f"(hi) : "l"(s))

// Device scratch
__device__ float g_S[B_HALF * D_DIM];     // s[b][j] = eps[b][j] / (2*pi*lam[j])
__device__ float g_M[B_HALF * D_DIM];     // mat[b][i]
__device__ float g_ws[B_HALF];            // -(w_s[b] + w_s[b+1024])
__device__ float g_wc[B_HALF];            //  (w_c[b] - w_c[b+1024])
__device__ float g_part[NG * N_ROWS * D_DIM];   // 32 MB partials

// ---------------------------------------------------------------------------
// Precompute S, mat, effective weights (unchanged from passing kernel).
// ---------------------------------------------------------------------------
__global__ void prep_kernel(const float* __restrict__ eps,
                            const float* __restrict__ lam,
                            const float* __restrict__ eta,
                            const float* __restrict__ w) {
    int idx = blockIdx.x * blockDim.x + threadIdx.x;
    if (idx < B_HALF * D_DIM) {
        int b = idx >> 6;
        int j = idx & 63;
        float l = lam[j];
        g_S[idx] = eps[idx] / (TWO_PI * l);
        float eta2 = eta[0] * eta[0];
        float m;
        if (j < 32) {
            m = eps[b * 64 + 32 + j] / lam[32 + j];
        } else {
            m = -eps[b * 64 + (j - 32)] / lam[j - 32] - eta2 * eps[idx] / l;
        }
        g_M[idx] = m;
    }
    if (idx < B_HALF) {
        g_ws[idx] = -(w[idx] + w[idx + B_HALF]);
        g_wc[idx] = w[2 * B_HALF + idx] - w[3 * B_HALF + idx];
    }
}

// ---------------------------------------------------------------------------
// Fused main kernel: register-tiled GEMM A (sim) + sincos + GEMM B (U @ M).
// Thread (ty = tid/16, tx = tid%16):
//   Phase A: 8 rows (4 rowpairs: rp = ty*4..+3) x 4 basis (b = tx*4..+3)
//   Phase B: 8 rows x 4 dims (d = tx*4..+3), K = 64 basis of this group
// ---------------------------------------------------------------------------
__global__ void __launch_bounds__(TB, 3)
main_kernel(const float* __restrict__ x) {
    extern __shared__ char smem[];
    float* sXf = (float*)(smem + OFF_X);   // [64 k][SX_STRIDE]  x transposed
    float* sSf = (float*)(smem + OFF_S);   // [64 k][SS_STRIDE]  s transposed
    float* sWs = (float*)(smem + OFF_W);   // [64]
    float* sWc = sWs + BT;                 // [64]
    u64*   sUu = (u64*)(smem + OFF_X);     // [64 b][SU_STRIDE]  (alias, phase B)
    float* sMf = (float*)(smem + OFF_S);   // [64 b][64]         (alias, phase B)

    const int tid = threadIdx.x;
    const int ty  = tid >> 4;              // 0..15
    const int tx  = tid & 15;              // 0..15
    const int bx  = blockIdx.x;
    const int g   = blockIdx.y;
    const int b0  = g * BT;

    // ---- Stage x tile transposed: sXf[k*SX_STRIDE + r] = x[row0+r][k] ----
    {
        const float4* xg = (const float4*)(x + (size_t)bx * ROWS_T * D_DIM);
        #pragma unroll
        for (int it = 0; it < 8; ++it) {
            int i  = tid + it * TB;        // float4 id, 2048 total
            int r  = i >> 4;
            int k4 = (i & 15) * 4;
            float4 v = xg[i];
            sXf[(k4 + 0) * SX_STRIDE + r] = v.x;
            sXf[(k4 + 1) * SX_STRIDE + r] = v.y;
            sXf[(k4 + 2) * SX_STRIDE + r] = v.z;
            sXf[(k4 + 3) * SX_STRIDE + r] = v.w;
        }
        const float4* sg = (const float4*)(g_S + (size_t)b0 * D_DIM);
        #pragma unroll
        for (int it = 0; it < 4; ++it) {
            int i  = tid + it * TB;        // float4 id, 1024 total
            int b  = i >> 4;
            int k4 = (i & 15) * 4;
            float4 v = sg[i];
            sSf[(k4 + 0) * SS_STRIDE + b] = v.x;
            sSf[(k4 + 1) * SS_STRIDE + b] = v.y;
            sSf[(k4 + 2) * SS_STRIDE + b] = v.z;
            sSf[(k4 + 3) * SS_STRIDE + b] = v.w;
        }
        if (tid < BT) {
            sWs[tid] = g_ws[b0 + tid];
            sWc[tid] = g_wc[b0 + tid];
        }
    }
    __syncthreads();

    // ---- Phase A: sim tile, rows packed 2/u64. acc[i=b_local][j=rowpair] ----
    u64 acc[4][4];
    #pragma unroll
    for (int i = 0; i < 4; ++i)
        #pragma unroll
        for (int j = 0; j < 4; ++j) acc[i][j] = 0ull;

    {
        const float* xbase = sXf + 8 * ty;       // rows 8*ty .. 8*ty+7
        const float* sbase = sSf + 4 * tx;       // basis 4*tx .. +3
        #pragma unroll 2
        for (int k = 0; k < 64; ++k) {
            // 8 row values (rowpairs) as 4 u64 via two 16B loads (broadcast in warp)
            const float4* xr = (const float4*)(xbase + k * SX_STRIDE);
            float4 xa = xr[0];
            float4 xb = xr[1];
            u64 xv0, xv1, xv2, xv3;
            PACK2(xv0, xa.x, xa.y);
            PACK2(xv1, xa.z, xa.w);
            PACK2(xv2, xb.x, xb.y);
            PACK2(xv3, xb.z, xb.w);
            // 4 s values, splat to both lanes
            float4 sv = *(const float4*)(sbase + k * SS_STRIDE);
            u64 s0, s1, s2, s3;
            PACK2(s0, sv.x, sv.x);
            PACK2(s1, sv.y, sv.y);
            PACK2(s2, sv.z, sv.z);
            PACK2(s3, sv.w, sv.w);
            FMA2(acc[0][0], xv0, s0, acc[0][0]);
            FMA2(acc[0][1], xv1, s0, acc[0][1]);
            FMA2(acc[0][2], xv2, s0, acc[0][2]);
            FMA2(acc[0][3], xv3, s0, acc[0][3]);
            FMA2(acc[1][0], xv0, s1, acc[1][0]);
            FMA2(acc[1][1], xv1, s1, acc[1][1]);
            FMA2(acc[1][2], xv2, s1, acc[1][2]);
            FMA2(acc[1][3], xv3, s1, acc[1][3]);
            FMA2(acc[2][0], xv0, s2, acc[2][0]);
            FMA2(acc[2][1], xv1, s2, acc[2][1]);
            FMA2(acc[2][2], xv2, s2, acc[2][2]);
            FMA2(acc[2][3], xv3, s2, acc[2][3]);
            FMA2(acc[3][0], xv0, s3, acc[3][0]);
            FMA2(acc[3][1], xv1, s3, acc[3][1]);
            FMA2(acc[3][2], xv2, s3, acc[3][2]);
            FMA2(acc[3][3], xv3, s3, acc[3][3]);
        }
    }

    // ---- Epilogue: acc (sim/2pi) -> u = sin*ws + cos*wc, in place ----
    #pragma unroll
    for (int i = 0; i < 4; ++i) {
        int bl = tx * 4 + i;
        float ws = sWs[bl];
        float wc = sWc[bl];
        #pragma unroll
        for (int j = 0; j < 4; ++j) {
            float p0, p1;
            UNPACK2(p0, p1, acc[i][j]);
            float r0 = p0 - rintf(p0);
            float r1 = p1 - rintf(p1);
            float t0 = r0 * TWO_PI;
            float t1 = r1 * TWO_PI;
            float u0 = __sinf(t0) * ws + __cosf(t0) * wc;
            float u1 = __sinf(t1) * ws + __cosf(t1) * wc;
            PACK2(acc[i][j], u0, u1);
        }
    }

    // All shared reads of sXf/sSf done by every warp before aliasing
    __syncthreads();

    // ---- Write U tile (rowpair-packed) + stage M tile into aliased smem ----
    #pragma unroll
    for (int i = 0; i < 4; ++i) {
        int bl = tx * 4 + i;
        #pragma unroll
        for (int j = 0; j < 4; ++j) {
            sUu[bl * SU_STRIDE + ty * 4 + j] = acc[i][j];
        }
    }
    {
        const float4* mg = (const float4*)(g_M + (size_t)b0 * D_DIM);
        float4* md = (float4*)sMf;
        #pragma unroll
        for (int it = 0; it < 4; ++it) {
            int i = tid + it * TB;
            md[i] = mg[i];
        }
    }
    __syncthreads();

    // ---- Phase B: f_partial = U @ M.  o[j=rowpair][i=d_local] ----
    u64 o[4][4];
    #pragma unroll
    for (int j = 0; j < 4; ++j)
        #pragma unroll
        for (int i = 0; i < 4; ++i) o[j][i] = 0ull;

    {
        const u64*   ubase = sUu + 4 * ty;
        const float* mbase = sMf + 4 * tx;
        #pragma unroll 2
        for (int b = 0; b < 64; ++b) {
            u64 uv0 = ubase[b * SU_STRIDE + 0];
            u64 uv1 = ubase[b * SU_STRIDE + 1];
            u64 uv2 = ubase[b * SU_STRIDE + 2];
            u64 uv3 = ubase[b * SU_STRIDE + 3];
            float4 mv = *(const float4*)(mbase + b * 64);
            u64 m0, m1, m2, m3;
            PACK2(m0, mv.x, mv.x);
            PACK2(m1, mv.y, mv.y);
            PACK2(m2, mv.z, mv.z);
            PACK2(m3, mv.w, mv.w);
            FMA2(o[0][0], uv0, m0, o[0][0]);
            FMA2(o[0][1], uv0, m1, o[0][1]);
            FMA2(o[0][2], uv0, m2, o[0][2]);
            FMA2(o[0][3], uv0, m3, o[0][3]);
            FMA2(o[1][0], uv1, m0, o[1][0]);
            FMA2(o[1][1], uv1, m1, o[1][1]);
            FMA2(o[1][2], uv1, m2, o[1][2]);
            FMA2(o[1][3], uv1, m3, o[1][3]);
            FMA2(o[2][0], uv2, m0, o[2][0]);
            FMA2(o[2][1], uv2, m1, o[2][1]);
            FMA2(o[2][2], uv2, m2, o[2][2]);
            FMA2(o[2][3], uv2, m3, o[2][3]);
            FMA2(o[3][0], uv3, m0, o[3][0]);
            FMA2(o[3][1], uv3, m1, o[3][1]);
            FMA2(o[3][2], uv3, m2, o[3][2]);
            FMA2(o[3][3], uv3, m3, o[3][3]);
        }
    }

    // ---- Store partials: rows 8*ty + 2*j (+lane), dims 4*tx .. +3 ----
    {
        float* pbase = g_part + ((size_t)g * N_ROWS + (size_t)bx * ROWS_T) * D_DIM;
        #pragma unroll
        for (int j = 0; j < 4; ++j) {
            float4 lo, hi;
            UNPACK2(lo.x, hi.x, o[j][0]);
            UNPACK2(lo.y, hi.y, o[j][1]);
            UNPACK2(lo.z, hi.z, o[j][2]);
            UNPACK2(lo.w, hi.w, o[j][3]);
            int row = 8 * ty + 2 * j;
            *(float4*)(pbase + (size_t)row * D_DIM + 4 * tx)       = lo;
            *(float4*)(pbase + (size_t)(row + 1) * D_DIM + 4 * tx) = hi;
        }
    }
}

// ---------------------------------------------------------------------------
// Reduce NG partial buffers into the output (vectorized).
// ---------------------------------------------------------------------------
__global__ void reduce_kernel(float4* __restrict__ out) {
    int idx = blockIdx.x * blockDim.x + threadIdx.x;   // < N*D/4 = 131072
    const float4* p = (const float4*)g_part;
    float4 s = p[idx];
    #pragma unroll
    for (int g = 1; g < NG; ++g) {
        float4 v = p[(size_t)g * (N_ROWS * D_DIM / 4) + idx];
        s.x += v.x; s.y += v.y; s.z += v.z; s.w += v.w;
    }
    out[idx] = s;
}

// ---------------------------------------------------------------------------
extern "C" void kernel_launch(void* const* d_in, const int* in_sizes, int n_in,
                              void* d_out, int out_size) {
    const float* x   = nullptr;
    const float* eps = nullptr;
    const float* lam = nullptr;
    const float* eta = nullptr;
    const float* w   = nullptr;
    int ones_seen = 0;
    for (int i = 0; i < n_in; ++i) {
        int sz = in_sizes[i];
        const float* p = (const float*)d_in[i];
        if      (sz == N_ROWS * D_DIM)     x   = p;
        else if (sz == 2 * B_HALF * D_DIM) eps = p;
        else if (sz == D_DIM)              lam = p;
        else if (sz == 4 * B_HALF)         w   = p;
        else if (sz == 1) {
            if (ones_seen == 1) eta = p;   // second size-1 input is eta
            ones_seen++;
        }
    }

    cudaFuncSetAttribute(main_kernel,
                         cudaFuncAttributeMaxDynamicSharedMemorySize, SMEM_BYTES);

    prep_kernel<<<(B_HALF * D_DIM + 255) / 256, 256>>>(eps, lam, eta, w);
    main_kernel<<<dim3(N_ROWS / ROWS_T, NG), TB, SMEM_BYTES>>>(x);
    reduce_kernel<<<(N_ROWS * D_DIM / 4 + 255) / 256, 256>>>((float4*)d_out);
}

// round 5
// speedup vs baseline: 1.6998x; 1.0068x over previous
#include <cuda_runtime.h>
#include <cstdint>

// Problem constants
#define N_ROWS 8192
#define D_DIM  64
#define B_HALF 1024          // epsilon = [tmp; -tmp] antisymmetry folds B=2048 -> 1024
#define TWO_PI 6.283185307179586f

// Tiling
#define TB      256          // threads per block
#define ROWS_T  128          // rows per block
#define BT      64           // basis per block
#define NG      (B_HALF / BT)   // 16 b-groups

// Shared layout (bytes)
#define SX_STRIDE 132        // floats per k-row of x tile (pad for banks, even for u64)
#define SS_STRIDE 68         // floats per k-row of s tile
#define SU_STRIDE 65         // u64 per b-row of u tile
#define OFF_X  0
#define OFF_S  (64 * SX_STRIDE * 4)                 // 33792
#define OFF_W  (OFF_S + 64 * SS_STRIDE * 4)         // 51200
#define SMEM_BYTES (OFF_W + 2 * BT * 4)             // 51712

typedef unsigned long long u64;

// Packed f32x2 math (Blackwell FFMA2 — full-rate fp32, 2 FMAs per instruction)
#define FMA2(d, a, b, c) asm("fma.rn.f32x2 %0, %1, %2, %3;" : "=l"(d) : "l"(a), "l"(b), "l"(c))
#define PACK2(d, lo, hi) asm("mov.b64 %0, {%1, %2};"        : "=l"(d) : "f"(lo), "f"(hi))
#define UNPACK2(lo, hi, s) asm("mov.b64 {%0, %1}, %2;"      : "=f"(lo), "=f"(hi) : "l"(s))

// Device scratch
__device__ float g_S[B_HALF * D_DIM];     // s[b][j] = eps[b][j] / (2*pi*lam[j])
__device__ float g_M[B_HALF * D_DIM];     // mat[b][i]
__device__ float g_ws[B_HALF];            // -(w_s[b] + w_s[b+1024])
__device__ float g_wc[B_HALF];            //  (w_c[b] - w_c[b+1024])
__device__ float g_part[NG * N_ROWS * D_DIM];   // 32 MB partials

// ---------------------------------------------------------------------------
// Precompute S, mat, effective weights (unchanged from passing kernel).
// ---------------------------------------------------------------------------
__global__ void prep_kernel(const float* __restrict__ eps,
                            const float* __restrict__ lam,
                            const float* __restrict__ eta,
                            const float* __restrict__ w) {
    int idx = blockIdx.x * blockDim.x + threadIdx.x;
    if (idx < B_HALF * D_DIM) {
        int b = idx >> 6;
        int j = idx & 63;
        float l = lam[j];
        g_S[idx] = eps[idx] / (TWO_PI * l);
        float eta2 = eta[0] * eta[0];
        float m;
        if (j < 32) {
            m = eps[b * 64 + 32 + j] / lam[32 + j];
        } else {
            m = -eps[b * 64 + (j - 32)] / lam[j - 32] - eta2 * eps[idx] / l;
        }
        g_M[idx] = m;
    }
    if (idx < B_HALF) {
        g_ws[idx] = -(w[idx] + w[idx + B_HALF]);
        g_wc[idx] = w[2 * B_HALF + idx] - w[3 * B_HALF + idx];
    }
}

// ---------------------------------------------------------------------------
// Fused main kernel: register-tiled GEMM A (sim) + sincos + GEMM B (U @ M).
// Thread (ty = tid/16, tx = tid%16):
//   Phase A: 8 rows (4 rowpairs: rp = ty*4..+3) x 4 basis (b = tx*4..+3)
//   Phase B: 8 rows x 4 dims (d = tx*4..+3), K = 64 basis of this group
// ---------------------------------------------------------------------------
__global__ void __launch_bounds__(TB, 3)
main_kernel(const float* __restrict__ x) {
    extern __shared__ char smem[];
    float* sXf = (float*)(smem + OFF_X);   // [64 k][SX_STRIDE]  x transposed
    float* sSf = (float*)(smem + OFF_S);   // [64 k][SS_STRIDE]  s transposed
    float* sWs = (float*)(smem + OFF_W);   // [64]
    float* sWc = sWs + BT;                 // [64]
    u64*   sUu = (u64*)(smem + OFF_X);     // [64 b][SU_STRIDE]  (alias, phase B)
    float* sMf = (float*)(smem + OFF_S);   // [64 b][64]         (alias, phase B)

    const int tid = threadIdx.x;
    const int ty  = tid >> 4;              // 0..15
    const int tx  = tid & 15;              // 0..15
    const int bx  = blockIdx.x;
    const int g   = blockIdx.y;
    const int b0  = g * BT;

    // ---- Stage x tile transposed: sXf[k*SX_STRIDE + r] = x[row0+r][k] ----
    {
        const float4* xg = (const float4*)(x + (size_t)bx * ROWS_T * D_DIM);
        #pragma unroll
        for (int it = 0; it < 8; ++it) {
            int i  = tid + it * TB;        // float4 id, 2048 total
            int r  = i >> 4;
            int k4 = (i & 15) * 4;
            float4 v = xg[i];
            sXf[(k4 + 0) * SX_STRIDE + r] = v.x;
            sXf[(k4 + 1) * SX_STRIDE + r] = v.y;
            sXf[(k4 + 2) * SX_STRIDE + r] = v.z;
            sXf[(k4 + 3) * SX_STRIDE + r] = v.w;
        }
        const float4* sg = (const float4*)(g_S + (size_t)b0 * D_DIM);
        #pragma unroll
        for (int it = 0; it < 4; ++it) {
            int i  = tid + it * TB;        // float4 id, 1024 total
            int b  = i >> 4;
            int k4 = (i & 15) * 4;
            float4 v = sg[i];
            sSf[(k4 + 0) * SS_STRIDE + b] = v.x;
            sSf[(k4 + 1) * SS_STRIDE + b] = v.y;
            sSf[(k4 + 2) * SS_STRIDE + b] = v.z;
            sSf[(k4 + 3) * SS_STRIDE + b] = v.w;
        }
        if (tid < BT) {
            sWs[tid] = g_ws[b0 + tid];
            sWc[tid] = g_wc[b0 + tid];
        }
    }
    __syncthreads();

    // ---- Phase A: sim tile, rows packed 2/u64. acc[i=b_local][j=rowpair] ----
    u64 acc[4][4];
    #pragma unroll
    for (int i = 0; i < 4; ++i)
        #pragma unroll
        for (int j = 0; j < 4; ++j) acc[i][j] = 0ull;

    {
        const float* xbase = sXf + 8 * ty;       // rows 8*ty .. 8*ty+7
        const float* sbase = sSf + 4 * tx;       // basis 4*tx .. +3
        #pragma unroll 2
        for (int k = 0; k < 64; ++k) {
            // 8 row values (rowpairs) as 4 u64 via two 16B loads (broadcast in warp)
            const float4* xr = (const float4*)(xbase + k * SX_STRIDE);
            float4 xa = xr[0];
            float4 xb = xr[1];
            u64 xv0, xv1, xv2, xv3;
            PACK2(xv0, xa.x, xa.y);
            PACK2(xv1, xa.z, xa.w);
            PACK2(xv2, xb.x, xb.y);
            PACK2(xv3, xb.z, xb.w);
            // 4 s values, splat to both lanes
            float4 sv = *(const float4*)(sbase + k * SS_STRIDE);
            u64 s0, s1, s2, s3;
            PACK2(s0, sv.x, sv.x);
            PACK2(s1, sv.y, sv.y);
            PACK2(s2, sv.z, sv.z);
            PACK2(s3, sv.w, sv.w);
            FMA2(acc[0][0], xv0, s0, acc[0][0]);
            FMA2(acc[0][1], xv1, s0, acc[0][1]);
            FMA2(acc[0][2], xv2, s0, acc[0][2]);
            FMA2(acc[0][3], xv3, s0, acc[0][3]);
            FMA2(acc[1][0], xv0, s1, acc[1][0]);
            FMA2(acc[1][1], xv1, s1, acc[1][1]);
            FMA2(acc[1][2], xv2, s1, acc[1][2]);
            FMA2(acc[1][3], xv3, s1, acc[1][3]);
            FMA2(acc[2][0], xv0, s2, acc[2][0]);
            FMA2(acc[2][1], xv1, s2, acc[2][1]);
            FMA2(acc[2][2], xv2, s2, acc[2][2]);
            FMA2(acc[2][3], xv3, s2, acc[2][3]);
            FMA2(acc[3][0], xv0, s3, acc[3][0]);
            FMA2(acc[3][1], xv1, s3, acc[3][1]);
            FMA2(acc[3][2], xv2, s3, acc[3][2]);
            FMA2(acc[3][3], xv3, s3, acc[3][3]);
        }
    }

    // ---- Epilogue: acc (sim/2pi) -> u = sin*ws + cos*wc, in place ----
    #pragma unroll
    for (int i = 0; i < 4; ++i) {
        int bl = tx * 4 + i;
        float ws = sWs[bl];
        float wc = sWc[bl];
        #pragma unroll
        for (int j = 0; j < 4; ++j) {
            float p0, p1;
            UNPACK2(p0, p1, acc[i][j]);
            float r0 = p0 - rintf(p0);
            float r1 = p1 - rintf(p1);
            float t0 = r0 * TWO_PI;
            float t1 = r1 * TWO_PI;
            float u0 = __sinf(t0) * ws + __cosf(t0) * wc;
            float u1 = __sinf(t1) * ws + __cosf(t1) * wc;
            PACK2(acc[i][j], u0, u1);
        }
    }

    // All shared reads of sXf/sSf done by every warp before aliasing
    __syncthreads();

    // ---- Write U tile (rowpair-packed) + stage M tile into aliased smem ----
    #pragma unroll
    for (int i = 0; i < 4; ++i) {
        int bl = tx * 4 + i;
        #pragma unroll
        for (int j = 0; j < 4; ++j) {
            sUu[bl * SU_STRIDE + ty * 4 + j] = acc[i][j];
        }
    }
    {
        const float4* mg = (const float4*)(g_M + (size_t)b0 * D_DIM);
        float4* md = (float4*)sMf;
        #pragma unroll
        for (int it = 0; it < 4; ++it) {
            int i = tid + it * TB;
            md[i] = mg[i];
        }
    }
    __syncthreads();

    // ---- Phase B: f_partial = U @ M.  o[j=rowpair][i=d_local] ----
    u64 o[4][4];
    #pragma unroll
    for (int j = 0; j < 4; ++j)
        #pragma unroll
        for (int i = 0; i < 4; ++i) o[j][i] = 0ull;

    {
        const u64*   ubase = sUu + 4 * ty;
        const float* mbase = sMf + 4 * tx;
        #pragma unroll 2
        for (int b = 0; b < 64; ++b) {
            u64 uv0 = ubase[b * SU_STRIDE + 0];
            u64 uv1 = ubase[b * SU_STRIDE + 1];
            u64 uv2 = ubase[b * SU_STRIDE + 2];
            u64 uv3 = ubase[b * SU_STRIDE + 3];
            float4 mv = *(const float4*)(mbase + b * 64);
            u64 m0, m1, m2, m3;
            PACK2(m0, mv.x, mv.x);
            PACK2(m1, mv.y, mv.y);
            PACK2(m2, mv.z, mv.z);
            PACK2(m3, mv.w, mv.w);
            FMA2(o[0][0], uv0, m0, o[0][0]);
            FMA2(o[0][1], uv0, m1, o[0][1]);
            FMA2(o[0][2], uv0, m2, o[0][2]);
            FMA2(o[0][3], uv0, m3, o[0][3]);
            FMA2(o[1][0], uv1, m0, o[1][0]);
            FMA2(o[1][1], uv1, m1, o[1][1]);
            FMA2(o[1][2], uv1, m2, o[1][2]);
            FMA2(o[1][3], uv1, m3, o[1][3]);
            FMA2(o[2][0], uv2, m0, o[2][0]);
            FMA2(o[2][1], uv2, m1, o[2][1]);
            FMA2(o[2][2], uv2, m2, o[2][2]);
            FMA2(o[2][3], uv2, m3, o[2][3]);
            FMA2(o[3][0], uv3, m0, o[3][0]);
            FMA2(o[3][1], uv3, m1, o[3][1]);
            FMA2(o[3][2], uv3, m2, o[3][2]);
            FMA2(o[3][3], uv3, m3, o[3][3]);
        }
    }

    // ---- Store partials: rows 8*ty + 2*j (+lane), dims 4*tx .. +3 ----
    {
        float* pbase = g_part + ((size_t)g * N_ROWS + (size_t)bx * ROWS_T) * D_DIM;
        #pragma unroll
        for (int j = 0; j < 4; ++j) {
            float4 lo, hi;
            UNPACK2(lo.x, hi.x, o[j][0]);
            UNPACK2(lo.y, hi.y, o[j][1]);
            UNPACK2(lo.z, hi.z, o[j][2]);
            UNPACK2(lo.w, hi.w, o[j][3]);
            int row = 8 * ty + 2 * j;
            *(float4*)(pbase + (size_t)row * D_DIM + 4 * tx)       = lo;
            *(float4*)(pbase + (size_t)(row + 1) * D_DIM + 4 * tx) = hi;
        }
    }
}

// ---------------------------------------------------------------------------
// Reduce NG partial buffers into the output (vectorized).
// ---------------------------------------------------------------------------
__global__ void reduce_kernel(float4* __restrict__ out) {
    int idx = blockIdx.x * blockDim.x + threadIdx.x;   // < N*D/4 = 131072
    const float4* p = (const float4*)g_part;
    float4 s = p[idx];
    #pragma unroll
    for (int g = 1; g < NG; ++g) {
        float4 v = p[(size_t)g * (N_ROWS * D_DIM / 4) + idx];
        s.x += v.x; s.y += v.y; s.z += v.z; s.w += v.w;
    }
    out[idx] = s;
}

// ---------------------------------------------------------------------------
extern "C" void kernel_launch(void* const* d_in, const int* in_sizes, int n_in,
                              void* d_out, int out_size) {
    const float* x   = nullptr;
    const float* eps = nullptr;
    const float* lam = nullptr;
    const float* eta = nullptr;
    const float* w   = nullptr;
    int ones_seen = 0;
    for (int i = 0; i < n_in; ++i) {
        int sz = in_sizes[i];
        const float* p = (const float*)d_in[i];
        if      (sz == N_ROWS * D_DIM)     x   = p;
        else if (sz == 2 * B_HALF * D_DIM) eps = p;
        else if (sz == D_DIM)              lam = p;
        else if (sz == 4 * B_HALF)         w   = p;
        else if (sz == 1) {
            if (ones_seen == 1) eta = p;   // second size-1 input is eta
            ones_seen++;
        }
    }

    cudaFuncSetAttribute(main_kernel,
                         cudaFuncAttributeMaxDynamicSharedMemorySize, SMEM_BYTES);

    prep_kernel<<<(B_HALF * D_DIM + 255) / 256, 256>>>(eps, lam, eta, w);
    main_kernel<<<dim3(N_ROWS / ROWS_T, NG), TB, SMEM_BYTES>>>(x);
    reduce_kernel<<<(N_ROWS * D_DIM / 4 + 255) / 256, 256>>>((float4*)d_out);
}